// round 11
// baseline (speedup 1.0000x reference)
#include <cuda_runtime.h>
#include <cuda_bf16.h>
#include <cstdint>

#define NN 50000
#define EE 800000
#define DD 128
#define LL 3
#define NB 196                        // scan blocks: ceil(50000/256)
#define WPN (LL * 256 * DD)           // 98304 weight elements
#define NR 50048                      // padded rows (391 * 128)

// ---------------- device scratch ----------------
__device__ float g_buf0[NN * DD];
__device__ float g_buf1[NN * DD];
__device__ int   g_rowptr[NN + 1];
__device__ int   g_counts[NN];
__device__ int   g_bsum[NB];
__device__ int   g_boff[NB];
__device__ int   g_srcs  [EE];
__device__ int   g_src_in[EE];
__device__ int   g_dst_in[EE];
__device__ int   g_is32;
__device__ int   g_arrive;
__device__ volatile int g_release;
// bf16 hi/lo planes, packed 2 cols per uint32, row stride 64 uint32.
// Pad rows [NN, NR) are never written -> stay zero.
__device__ uint32_t g_Ah[NR * 64];    // agg planes
__device__ uint32_t g_Al[NR * 64];
__device__ uint32_t g_Xh[NR * 64];    // x (layer input) planes
__device__ uint32_t g_Xl[NR * 64];
// transposed bf16 weights: [layer][n=128][k=256] (k<128 -> Wrel, else Wroot)
__device__ unsigned short g_Bth[LL * DD * 2 * DD];
__device__ unsigned short g_Btl[LL * DD * 2 * DD];

__device__ __forceinline__ uint32_t pack_bf2f(float a, float b) {
    __nv_bfloat16 ha = __float2bfloat16(a), hb = __float2bfloat16(b);
    uint16_t ua = *(uint16_t*)&ha, ub = *(uint16_t*)&hb;
    return (uint32_t)ua | ((uint32_t)ub << 16);
}
__device__ __forceinline__ uint32_t pack_lo2f(float a, float b, float* la, float* lb) {
    float ha = __bfloat162float(__float2bfloat16(a));
    float hb = __bfloat162float(__float2bfloat16(b));
    *la = a - ha; *lb = b - hb;
    return pack_bf2f(*la, *lb);
}

// ---------------- init: counts + detect + weight prep + x planes -------------
__global__ void init_kernel(const unsigned int* __restrict__ w,
                            const float* __restrict__ Wrel,
                            const float* __restrict__ Wroot,
                            const float* __restrict__ x) {
    int i = blockIdx.x * blockDim.x + threadIdx.x;
    int stride = gridDim.x * blockDim.x;
    if (i == 0) { g_is32 = 0; g_arrive = 0; g_release = 0; }
    if (i < NN) g_counts[i] = 0;
    if (i < 4096) {
        unsigned int acc = 0;
        #pragma unroll
        for (int j = 0; j < 4; j++) acc |= w[2 * (i * 4 + j) + 1];
        if (acc) g_is32 = 1;
    }
    if (i < WPN) {
        int l = i / (256 * DD);
        int r = i - l * 256 * DD;
        int k = r / DD;
        int n = r - k * DD;
        float wv = (k < DD) ? Wrel[(size_t)l * DD * DD + k * DD + n]
                            : Wroot[(size_t)l * DD * DD + (k - DD) * DD + n];
        __nv_bfloat16 hi = __float2bfloat16(wv);
        float lo = wv - __bfloat162float(hi);
        __nv_bfloat16 lob = __float2bfloat16(lo);
        size_t o = (size_t)l * DD * 256 + (size_t)n * 256 + k;
        g_Bth[o] = *(unsigned short*)&hi;
        g_Btl[o] = *(unsigned short*)&lob;
    }
    // x -> bf16 hi/lo planes (layer 0 input)
    for (int p = i; p < NN * 64; p += stride) {
        int row = p >> 6, q = p & 63;
        float a = x[(size_t)row * DD + 2 * q];
        float b = x[(size_t)row * DD + 2 * q + 1];
        float la, lb;
        uint32_t lo = pack_lo2f(a, b, &la, &lb);
        g_Xh[p] = pack_bf2f(a, b);
        g_Xl[p] = lo;
    }
}

__global__ void convert_hist_kernel(const void* __restrict__ edges) {
    int e = blockIdx.x * blockDim.x + threadIdx.x;
    if (e >= EE) return;
    int s, d;
    if (g_is32) {
        const int* p = (const int*)edges;
        s = p[e]; d = p[EE + e];
    } else {
        const long long* p = (const long long*)edges;
        s = (int)p[e]; d = (int)p[EE + e];
    }
    g_src_in[e] = s;
    g_dst_in[e] = d;
    atomicAdd(&g_counts[d], 1);
}

// ---------------- single-kernel scan (grid-sync via atomic ticket) -----------
__global__ void scan_kernel() {
    __shared__ int s[256];
    __shared__ int sel;
    int b = blockIdx.x, t = threadIdx.x;
    int i = b * 256 + t;
    int v = (i < NN) ? g_counts[i] : 0;
    s[t] = v;
    __syncthreads();
    #pragma unroll
    for (int o = 1; o < 256; o <<= 1) {
        int u = (t >= o) ? s[t - o] : 0;
        __syncthreads();
        s[t] += u;
        __syncthreads();
    }
    if (t == 255) {
        g_bsum[b] = s[255];
        __threadfence();
        int tk = atomicAdd(&g_arrive, 1);
        sel = (tk == NB - 1);
    }
    __syncthreads();
    if (sel) {
        __shared__ int m[256];
        int mv = (t < NB) ? g_bsum[t] : 0;
        m[t] = mv;
        __syncthreads();
        #pragma unroll
        for (int o = 1; o < 256; o <<= 1) {
            int u = (t >= o) ? m[t - o] : 0;
            __syncthreads();
            m[t] += u;
            __syncthreads();
        }
        if (t < NB) g_boff[t] = m[t] - mv;
        if (t == 255) g_rowptr[NN] = m[255];
        __threadfence();
        __syncthreads();
        if (t == 0) g_release = 1;
    } else if (t == 0) {
        while (g_release == 0) { }
    }
    __syncthreads();
    __threadfence();
    if (i < NN) {
        g_rowptr[i] = g_boff[b] + s[t] - v;
        g_counts[i] = 0;
    }
}

__global__ void fill_kernel() {
    int e = blockIdx.x * blockDim.x + threadIdx.x;
    if (e >= EE) return;
    int d = g_dst_in[e];
    int pos = g_rowptr[d] + atomicAdd(&g_counts[d], 1);
    g_srcs[pos] = g_src_in[e];
}

// ---------------- aggregation: warp per node -> bf16 hi/lo planes ------------
__global__ void agg_kernel(const float* __restrict__ x) {
    int gw   = (blockIdx.x * blockDim.x + threadIdx.x) >> 5;
    int lane = threadIdx.x & 31;
    if (gw >= NN) return;
    int beg = g_rowptr[gw], end = g_rowptr[gw + 1];
    float4 acc = make_float4(0.f, 0.f, 0.f, 0.f);
    const float* xb = x + lane * 4;
    int e = beg;
    for (; e + 3 < end; e += 4) {
        int s0 = g_srcs[e], s1 = g_srcs[e+1], s2 = g_srcs[e+2], s3 = g_srcs[e+3];
        float4 v0 = *(const float4*)(xb + (size_t)s0 * DD);
        float4 v1 = *(const float4*)(xb + (size_t)s1 * DD);
        float4 v2 = *(const float4*)(xb + (size_t)s2 * DD);
        float4 v3 = *(const float4*)(xb + (size_t)s3 * DD);
        acc.x += (v0.x + v1.x) + (v2.x + v3.x);
        acc.y += (v0.y + v1.y) + (v2.y + v3.y);
        acc.z += (v0.z + v1.z) + (v2.z + v3.z);
        acc.w += (v0.w + v1.w) + (v2.w + v3.w);
    }
    for (; e < end; e++) {
        float4 v = *(const float4*)(xb + (size_t)g_srcs[e] * DD);
        acc.x += v.x; acc.y += v.y; acc.z += v.z; acc.w += v.w;
    }
    float lx, ly, lz, lw;
    uint32_t lo0 = pack_lo2f(acc.x, acc.y, &lx, &ly);
    uint32_t lo1 = pack_lo2f(acc.z, acc.w, &lz, &lw);
    size_t base = (size_t)gw * 64 + 2 * lane;
    g_Ah[base]     = pack_bf2f(acc.x, acc.y);
    g_Ah[base + 1] = pack_bf2f(acc.z, acc.w);
    g_Al[base]     = lo0;
    g_Al[base + 1] = lo1;
}

// ---------------- GEMM: cp.async planes -> smem -> ldmatrix -> mma.sync ------
// out[m][n] = sum_k A[m][k] W[k][n] + bias[n];  A = [agg | x] (virtual K=256),
// all operands pre-split bf16 hi/lo. acc += AhBh + AhBl + AlBh.
// BM=128, BN=128, BK=32, 256 threads, warp tile 64x32, 2 CTAs/SM.

#define ROWB 80
#define BUFB 40960
#define OFF_AH 0
#define OFF_AL 10240
#define OFF_BH 20480
#define OFF_BL 30720

__device__ __forceinline__ uint32_t smem_u32(const void* p) {
    uint32_t a;
    asm("{ .reg .u64 t; cvta.to.shared.u64 t, %1; cvt.u32.u64 %0, t; }" : "=r"(a) : "l"(p));
    return a;
}

#define LDSM4(r, a)                                                              \
    asm volatile("ldmatrix.sync.aligned.m8n8.x4.shared.b16 {%0,%1,%2,%3}, [%4];" \
        : "=r"((r)[0]), "=r"((r)[1]), "=r"((r)[2]), "=r"((r)[3]) : "r"(a))

__device__ __forceinline__ void mma16816(float* c, const uint32_t* a, const uint32_t* b) {
    asm volatile(
        "mma.sync.aligned.m16n8k16.row.col.f32.bf16.bf16.f32 "
        "{%0,%1,%2,%3}, {%4,%5,%6,%7}, {%8,%9}, {%0,%1,%2,%3};"
        : "+f"(c[0]), "+f"(c[1]), "+f"(c[2]), "+f"(c[3])
        : "r"(a[0]), "r"(a[1]), "r"(a[2]), "r"(a[3]), "r"(b[0]), "r"(b[1]));
}

__global__ void __launch_bounds__(256, 2) gemm_mma_kernel(
    int layer,
    const float* __restrict__ bias,
    float* __restrict__ out,
    uint32_t* __restrict__ xph,     // next-layer x planes (null on last layer)
    uint32_t* __restrict__ xpl)
{
    extern __shared__ char smem[];
    int tid  = threadIdx.x;
    int wid  = tid >> 5;
    int lane = tid & 31;
    int g    = lane >> 2;
    int t    = lane & 3;
    int row0 = blockIdx.x * 128;
    int m0w  = (wid >> 2) * 64;
    int n0w  = (wid & 3) * 32;

    uint32_t sb = smem_u32(smem);
    uint32_t aoff_c = (uint32_t)(m0w + (lane & 15)) * ROWB + ((lane >> 4) << 4);
    uint32_t boff_c = (uint32_t)(n0w + ((lane >> 4) << 3) + (lane & 7)) * ROWB
                    + (((lane >> 3) & 1) << 4);

    const uint32_t* Bth32 = (const uint32_t*)(g_Bth + (size_t)layer * DD * 256);
    const uint32_t* Btl32 = (const uint32_t*)(g_Btl + (size_t)layer * DD * 256);

    float acc[4][4][4];
    #pragma unroll
    for (int i = 0; i < 4; i++)
        #pragma unroll
        for (int j = 0; j < 4; j++)
            #pragma unroll
            for (int q = 0; q < 4; q++) acc[i][j][q] = 0.f;

    // issue all cp.async copies for chunk c into buffer buf
    auto issue_chunk = [&](int c, int buf) {
        uint32_t base = sb + buf * BUFB;
        int cl = c & 3;                           // chunk-local col for A planes
        const uint32_t* Ah = (c < 4) ? g_Ah : g_Xh;
        const uint32_t* Al = (c < 4) ? g_Al : g_Xl;
        #pragma unroll
        for (int j = 0; j < 8; j++) {
            int idx = j * 256 + tid;              // 0..2047
            int tile = idx >> 9;                  // 0:Ah 1:Al 2:Bh 3:Bl
            int r = (idx >> 2) & 127;
            int q = idx & 3;
            uint32_t dst = base + tile * 10240 + (uint32_t)r * ROWB + q * 16;
            const uint32_t* src;
            if (tile == 0)      src = Ah + (size_t)(row0 + r) * 64 + cl * 16 + q * 4;
            else if (tile == 1) src = Al + (size_t)(row0 + r) * 64 + cl * 16 + q * 4;
            else if (tile == 2) src = Bth32 + r * 128 + c * 16 + q * 4;
            else                src = Btl32 + r * 128 + c * 16 + q * 4;
            asm volatile("cp.async.cg.shared.global [%0], [%1], 16;"
                         :: "r"(dst), "l"(src));
        }
        asm volatile("cp.async.commit_group;");
    };

    issue_chunk(0, 0);

    #pragma unroll 1
    for (int c = 0; c < 8; c++) {
        __syncthreads();                          // all warps done with chunk c-1
        if (c < 7) issue_chunk(c + 1, (c + 1) & 1);
        if (c < 7) asm volatile("cp.async.wait_group 1;");
        else       asm volatile("cp.async.wait_group 0;");
        __syncthreads();                          // chunk c visible to all

        uint32_t bu = sb + (c & 1) * BUFB;
        #pragma unroll
        for (int s = 0; s < 2; s++) {
            uint32_t ks = s * 32;
            uint32_t ahq[4][4], alq[4][4], bhq[2][4], blq[2][4];
            #pragma unroll
            for (int mt = 0; mt < 4; mt++) {
                uint32_t adr = bu + OFF_AH + aoff_c + mt * (16 * ROWB) + ks;
                LDSM4(ahq[mt], adr);
                LDSM4(alq[mt], adr + (OFF_AL - OFF_AH));
            }
            #pragma unroll
            for (int p = 0; p < 2; p++) {
                uint32_t bdr = bu + OFF_BH + boff_c + p * (16 * ROWB) + ks;
                LDSM4(bhq[p], bdr);
                LDSM4(blq[p], bdr + (OFF_BL - OFF_BH));
            }
            #pragma unroll
            for (int mt = 0; mt < 4; mt++)
                #pragma unroll
                for (int p = 0; p < 2; p++) {
                    mma16816(acc[mt][2*p],   ahq[mt], &bhq[p][0]);
                    mma16816(acc[mt][2*p],   ahq[mt], &blq[p][0]);
                    mma16816(acc[mt][2*p],   alq[mt], &bhq[p][0]);
                    mma16816(acc[mt][2*p+1], ahq[mt], &bhq[p][2]);
                    mma16816(acc[mt][2*p+1], ahq[mt], &blq[p][2]);
                    mma16816(acc[mt][2*p+1], alq[mt], &bhq[p][2]);
                }
        }
    }

    // epilogue: bias + fp32 out + (optional) next-layer x planes
    #pragma unroll
    for (int nt = 0; nt < 4; nt++) {
        int col = n0w + nt * 8 + 2 * t;           // even
        float b0 = bias[col], b1 = bias[col + 1];
        #pragma unroll
        for (int mt = 0; mt < 4; mt++) {
            int r = row0 + m0w + mt * 16 + g;
            if (r < NN) {
                float ox = acc[mt][nt][0] + b0, oy = acc[mt][nt][1] + b1;
                *(float2*)(out + (size_t)r * DD + col) = make_float2(ox, oy);
                if (xph) {
                    float la, lb;
                    uint32_t lo = pack_lo2f(ox, oy, &la, &lb);
                    size_t pi = (size_t)r * 64 + (col >> 1);
                    xph[pi] = pack_bf2f(ox, oy);
                    xpl[pi] = lo;
                }
            }
            if (r + 8 < NN) {
                float ox = acc[mt][nt][2] + b0, oy = acc[mt][nt][3] + b1;
                *(float2*)(out + (size_t)(r + 8) * DD + col) = make_float2(ox, oy);
                if (xph) {
                    float la, lb;
                    uint32_t lo = pack_lo2f(ox, oy, &la, &lb);
                    size_t pi = (size_t)(r + 8) * 64 + (col >> 1);
                    xph[pi] = pack_bf2f(ox, oy);
                    xpl[pi] = lo;
                }
            }
        }
    }
}

// ---------------- launch ----------------
extern "C" void kernel_launch(void* const* d_in, const int* in_sizes, int n_in,
                              void* d_out, int out_size) {
    const float* x     = (const float*)d_in[0];
    const void*  edges = d_in[1];
    const float* Wrel  = (const float*)d_in[2];
    const float* Wroot = (const float*)d_in[3];
    const float* bias  = (const float*)d_in[4];
    float*       out   = (float*)d_out;

    float *buf0, *buf1;
    uint32_t *xh, *xl;
    cudaGetSymbolAddress((void**)&buf0, g_buf0);
    cudaGetSymbolAddress((void**)&buf1, g_buf1);
    cudaGetSymbolAddress((void**)&xh, g_Xh);
    cudaGetSymbolAddress((void**)&xl, g_Xl);

    cudaFuncSetAttribute(gemm_mma_kernel,
                         cudaFuncAttributeMaxDynamicSharedMemorySize, 2 * BUFB);

    const int T = 256;
    int gbE = (EE + T - 1) / T;

    init_kernel<<<1024, T>>>((const unsigned int*)edges, Wrel, Wroot, x);
    convert_hist_kernel<<<gbE, T>>>(edges);
    scan_kernel<<<NB, 256>>>();
    fill_kernel<<<gbE, T>>>();

    int aggBlocks  = (NN * 32 + T - 1) / T;
    int gemmBlocks = (NN + 127) / 128;   // 391

    const float* cur = x;
    float* outs[LL] = { buf0, buf1, out };
    for (int l = 0; l < LL; l++) {
        agg_kernel<<<aggBlocks, T>>>(cur);
        gemm_mma_kernel<<<gemmBlocks, T, 2 * BUFB>>>(
            l, bias + (size_t)l * DD, outs[l],
            (l < LL - 1) ? xh : nullptr,
            (l < LL - 1) ? xl : nullptr);
        cur = outs[l];
    }
}